// round 2
// baseline (speedup 1.0000x reference)
#include <cuda_runtime.h>
#include <cstdint>

#define B_    1024
#define IN_   4096
#define OUT_  4096
#define KDIM  64
#define TOPK_ 64

// 64 MB transposed-weight scratch: WT[i][o] = W[o][i]. Static __device__ global
// (allowed; no runtime allocation).
__device__ float g_WT[(size_t)IN_ * OUT_];

// ---------------------------------------------------------------------------
// Kernel 1: tiled transpose W(OUT,IN) -> WT(IN,OUT), fully coalesced both ways
// ---------------------------------------------------------------------------
__global__ __launch_bounds__(256) void transpose_kernel(const float* __restrict__ W) {
    __shared__ float tile[32][33];
    int bx = blockIdx.x * 32;   // i (column of W)
    int by = blockIdx.y * 32;   // o (row of W)
    int tx = threadIdx.x, ty = threadIdx.y;  // 32 x 8
#pragma unroll
    for (int j = 0; j < 32; j += 8)
        tile[ty + j][tx] = W[(size_t)(by + ty + j) * IN_ + bx + tx];
    __syncthreads();
#pragma unroll
    for (int j = 0; j < 32; j += 8)
        g_WT[(size_t)(bx + ty + j) * OUT_ + by + tx] = tile[tx][ty + j];
}

// ---------------------------------------------------------------------------
// Monotone float<->uint key (total order matching float compare)
// ---------------------------------------------------------------------------
__device__ __forceinline__ unsigned int flipf(float f) {
    unsigned int u = __float_as_uint(f);
    return (u & 0x80000000u) ? ~u : (u | 0x80000000u);
}
__device__ __forceinline__ float unflipf(unsigned int key) {
    unsigned int u = (key & 0x80000000u) ? (key & 0x7FFFFFFFu) : ~key;
    return __uint_as_float(u);
}

// ---------------------------------------------------------------------------
// Kernel 2: one block per batch row b.
//   Phase A: gathered mat-vec, fp32, accumulators in registers (16/thread)
//   Phase B: exact top-64 via 4-level radix select + bitonic sort of survivors
// ---------------------------------------------------------------------------
__global__ __launch_bounds__(256) void router_kernel(
    const float* __restrict__ x,
    const float* __restrict__ bias,
    const int*   __restrict__ prev_idx,
    float*       __restrict__ out,
    int write_indices)
{
    __shared__ float sx[KDIM];
    __shared__ int   sidx[KDIM];
    __shared__ float svals[OUT_];            // 16 KB
    __shared__ unsigned int hist[256];
    __shared__ unsigned long long sel[128];
    __shared__ int s_t;
    __shared__ int s_cnt;

    const int b   = blockIdx.x;
    const int tid = threadIdx.x;

    if (tid < KDIM) {
        sx[tid]   = x[b * KDIM + tid];
        sidx[tid] = prev_idx[b * KDIM + tid];
    }
    if (tid == 0) s_cnt = 0;
    __syncthreads();

    // ---------------- Phase A: gathered mat-vec ----------------
    const float4* WT4 = reinterpret_cast<const float4*>(g_WT);
    float4 a0 = make_float4(0.f, 0.f, 0.f, 0.f);
    float4 a1 = a0, a2 = a0, a3 = a0;

#pragma unroll 2
    for (int k = 0; k < KDIM; k++) {
        const float xk = sx[k];
        const float4* row = WT4 + (size_t)sidx[k] * (OUT_ / 4);
        float4 w;
        w = row[tid + 0 * 256];
        a0.x += w.x * xk; a0.y += w.y * xk; a0.z += w.z * xk; a0.w += w.w * xk;
        w = row[tid + 1 * 256];
        a1.x += w.x * xk; a1.y += w.y * xk; a1.z += w.z * xk; a1.w += w.w * xk;
        w = row[tid + 2 * 256];
        a2.x += w.x * xk; a2.y += w.y * xk; a2.z += w.z * xk; a2.w += w.w * xk;
        w = row[tid + 3 * 256];
        a3.x += w.x * xk; a3.y += w.y * xk; a3.z += w.z * xk; a3.w += w.w * xk;
    }

    // bias add
    const float4* b4 = reinterpret_cast<const float4*>(bias);
    float4 bb;
    bb = b4[tid + 0 * 256]; a0.x += bb.x; a0.y += bb.y; a0.z += bb.z; a0.w += bb.w;
    bb = b4[tid + 1 * 256]; a1.x += bb.x; a1.y += bb.y; a1.z += bb.z; a1.w += bb.w;
    bb = b4[tid + 2 * 256]; a2.x += bb.x; a2.y += bb.y; a2.z += bb.z; a2.w += bb.w;
    bb = b4[tid + 3 * 256]; a3.x += bb.x; a3.y += bb.y; a3.z += bb.z; a3.w += bb.w;

    float4* sv4 = reinterpret_cast<float4*>(svals);
    sv4[tid + 0 * 256] = a0;
    sv4[tid + 1 * 256] = a1;
    sv4[tid + 2 * 256] = a2;
    sv4[tid + 3 * 256] = a3;
    __syncthreads();

    // ---------------- Phase B1: 4-level radix select of top-64 threshold ----
    unsigned int prefix = 0;
    int above = 0;
#pragma unroll 1
    for (int level = 0; level < 4; level++) {
        const int shift = 24 - level * 8;
        const unsigned int mask = (level == 0) ? 0u : (0xFFFFFFFFu << (shift + 8));

        hist[tid] = 0;
        __syncthreads();
        for (int o = tid; o < OUT_; o += 256) {
            unsigned int key = flipf(svals[o]);
            if ((key & mask) == prefix)
                atomicAdd(&hist[(key >> shift) & 0xFFu], 1u);
        }
        __syncthreads();
        // inclusive suffix sum: hist[j] = sum_{i>=j} hist[i]
        for (int d = 1; d < 256; d <<= 1) {
            unsigned int v = hist[tid];
            unsigned int w = (tid + d < 256) ? hist[tid + d] : 0u;
            __syncthreads();
            hist[tid] = v + w;
            __syncthreads();
        }
        // find threshold byte t: above+SS[t] >= TOPK > above+SS[t+1]
        {
            unsigned int ss  = hist[tid];
            unsigned int ssn = (tid < 255) ? hist[tid + 1] : 0u;
            if (above + (int)ss >= TOPK_ && above + (int)ssn < TOPK_)
                s_t = tid;
        }
        __syncthreads();
        const int t = s_t;
        above += (t < 255) ? (int)hist[t + 1] : 0;
        prefix |= ((unsigned int)t) << shift;
        __syncthreads();  // protect hist before next-level clear
    }
    const unsigned int T = prefix;  // exact 64th-largest key

    // ---------------- Phase B2: collect survivors (key >= T) ---------------
    for (int o = tid; o < OUT_; o += 256) {
        unsigned int key = flipf(svals[o]);
        if (key >= T) {
            int pos = atomicAdd(&s_cnt, 1);
            if (pos < 128)
                sel[pos] = ((unsigned long long)key << 32) |
                           (unsigned long long)(0xFFFFFFFFu - (unsigned int)o);
        }
    }
    __syncthreads();
    {
        int cnt = s_cnt;
        if (tid < 128 && tid >= cnt) sel[tid] = 0ull;  // pad with minimum key
    }
    __syncthreads();

    // ---------------- Phase B3: bitonic sort 128 descending -----------------
    // Packed key: (mono_key << 32) | (~idx)  => descending sort gives
    // values descending, ties broken by smaller index first (matches jax).
    for (int size = 2; size <= 128; size <<= 1) {
        for (int stride = size >> 1; stride > 0; stride >>= 1) {
            __syncthreads();
            if (tid < 128) {
                int partner = tid ^ stride;
                if (partner > tid) {
                    unsigned long long va = sel[tid], vb = sel[partner];
                    bool desc = ((tid & size) == 0);
                    if (desc ? (va < vb) : (va > vb)) {
                        sel[tid] = vb;
                        sel[partner] = va;
                    }
                }
            }
        }
    }
    __syncthreads();

    // ---------------- Output: vals then indices (as float) ------------------
    if (tid < TOPK_) {
        unsigned long long p = sel[tid];
        unsigned int key = (unsigned int)(p >> 32);
        unsigned int idx = 0xFFFFFFFFu - (unsigned int)(p & 0xFFFFFFFFull);
        out[b * TOPK_ + tid] = unflipf(key);
        if (write_indices)
            out[(size_t)B_ * TOPK_ + b * TOPK_ + tid] = (float)idx;
    }
}

// ---------------------------------------------------------------------------
// Launch: transpose (every call; graph-replay deterministic) then fused kernel
// ---------------------------------------------------------------------------
extern "C" void kernel_launch(void* const* d_in, const int* in_sizes, int n_in,
                              void* d_out, int out_size) {
    const float* x        = (const float*)d_in[0];  // (B, K) f32
    const float* W        = (const float*)d_in[1];  // (OUT, IN) f32
    const float* bias     = (const float*)d_in[2];  // (OUT,) f32
    const int*   prev_idx = (const int*)d_in[3];    // (B, K) i32
    float* out = (float*)d_out;

    int write_indices = (out_size >= 2 * B_ * TOPK_) ? 1 : 0;

    dim3 tpose_block(32, 8);
    dim3 tpose_grid(IN_ / 32, OUT_ / 32);
    transpose_kernel<<<tpose_grid, tpose_block>>>(W);

    router_kernel<<<B_, 256>>>(x, bias, prev_idx, out, write_indices);
}

// round 4
// speedup vs baseline: 1.1729x; 1.1729x over previous
#include <cuda_runtime.h>
#include <cuda_fp16.h>
#include <cstdint>

#define B_    1024
#define IN_   4096
#define OUT_  4096
#define KDIM  64
#define TOPK_ 64
#define CAND_ 96      // candidate margin for fp16 pre-ranking (exact fixup after)

// 32 MB transposed fp16 weights: WT16[i][o] = (half)W[o][i]
__device__ __half g_WT16[(size_t)IN_ * OUT_];
// candidate scratch
__device__ unsigned int g_cand[B_][128];
__device__ int          g_cnt[B_];

// ---------------------------------------------------------------------------
// Kernel 1: transpose + convert W(OUT,IN) fp32 -> WT16(IN,OUT) fp16
// 64x64 tiles, float4 reads, 8B (4-half) writes
// ---------------------------------------------------------------------------
__global__ __launch_bounds__(256) void transpose16_kernel(const float* __restrict__ W) {
    __shared__ float tile[64][65];
    const int bx = blockIdx.x * 64;   // i
    const int by = blockIdx.y * 64;   // o
    const int tid = threadIdx.x;

    const float4* W4 = reinterpret_cast<const float4*>(W);
#pragma unroll
    for (int j = 0; j < 4; j++) {
        int f4_id = tid + 256 * j;          // 0..1023
        int o_r = f4_id >> 4;               // 0..63
        int qi  = f4_id & 15;               // 0..15
        float4 v = W4[(size_t)(by + o_r) * (IN_ / 4) + (bx >> 2) + qi];
        tile[o_r][qi * 4 + 0] = v.x;
        tile[o_r][qi * 4 + 1] = v.y;
        tile[o_r][qi * 4 + 2] = v.z;
        tile[o_r][qi * 4 + 3] = v.w;
    }
    __syncthreads();

#pragma unroll
    for (int j = 0; j < 4; j++) {
        int cid = tid + 256 * j;            // 0..1023
        int i_r = cid >> 4;                 // 0..63
        int c   = cid & 15;                 // 0..15 (4-half chunk within o)
        __half2 h0 = __floats2half2_rn(tile[c * 4 + 0][i_r], tile[c * 4 + 1][i_r]);
        __half2 h1 = __floats2half2_rn(tile[c * 4 + 2][i_r], tile[c * 4 + 3][i_r]);
        uint2 pack;
        pack.x = *reinterpret_cast<unsigned int*>(&h0);
        pack.y = *reinterpret_cast<unsigned int*>(&h1);
        uint2* dst = reinterpret_cast<uint2*>(&g_WT16[(size_t)(bx + i_r) * OUT_ + by + c * 4]);
        *dst = pack;
    }
}

// ---------------------------------------------------------------------------
// Monotone float<->uint key
// ---------------------------------------------------------------------------
__device__ __forceinline__ unsigned int flipf(float f) {
    unsigned int u = __float_as_uint(f);
    return (u & 0x80000000u) ? ~u : (u | 0x80000000u);
}
__device__ __forceinline__ float unflipf(unsigned int key) {
    unsigned int u = (key & 0x80000000u) ? (key & 0x7FFFFFFFu) : ~key;
    return __uint_as_float(u);
}

// ---------------------------------------------------------------------------
// Kernel 2: fp16 gather mat-vec (fp32 accumulate) + radix-select top-CAND_
// candidates per row -> g_cand. One block per b.
// ---------------------------------------------------------------------------
__global__ __launch_bounds__(256) void gather16_kernel(
    const float* __restrict__ x,
    const float* __restrict__ bias,
    const int*   __restrict__ prev_idx)
{
    __shared__ float sx[KDIM];
    __shared__ int   sidx[KDIM];
    __shared__ float svals[OUT_];            // 16 KB
    __shared__ unsigned int hist[256];
    __shared__ int s_t;
    __shared__ int s_cnt;

    const int b   = blockIdx.x;
    const int tid = threadIdx.x;

    if (tid < KDIM) {
        sx[tid]   = x[b * KDIM + tid];
        sidx[tid] = prev_idx[b * KDIM + tid];
    }
    if (tid == 0) s_cnt = 0;
    __syncthreads();

    // ---------------- Phase A: gathered mat-vec (fp16 weights) --------------
    // Each thread owns 16 outputs: uint4 chunks at (tid) and (tid+256);
    // chunk u covers outputs 8u..8u+7.
    float a[16];
#pragma unroll
    for (int e = 0; e < 16; e++) a[e] = 0.f;

#pragma unroll 2
    for (int k = 0; k < KDIM; k++) {
        const float xk = sx[k];
        const uint4* row = reinterpret_cast<const uint4*>(g_WT16 + (size_t)sidx[k] * OUT_);
        uint4 u0 = row[tid];
        uint4 u1 = row[tid + 256];
        const __half2* h0 = reinterpret_cast<const __half2*>(&u0);
        const __half2* h1 = reinterpret_cast<const __half2*>(&u1);
#pragma unroll
        for (int p = 0; p < 4; p++) {
            float2 f0 = __half22float2(h0[p]);
            float2 f1 = __half22float2(h1[p]);
            a[p * 2 + 0] += f0.x * xk;
            a[p * 2 + 1] += f0.y * xk;
            a[8 + p * 2 + 0] += f1.x * xk;
            a[8 + p * 2 + 1] += f1.y * xk;
        }
    }

    // bias add + store approx values to smem
    {
        const float4* b4 = reinterpret_cast<const float4*>(bias);
        float4* sv4 = reinterpret_cast<float4*>(svals);
#pragma unroll
        for (int j = 0; j < 2; j++) {
            int cidx = tid + j * 256;           // uint4 chunk id -> 2 float4 slots
            float4 bb0 = b4[2 * cidx + 0];
            float4 bb1 = b4[2 * cidx + 1];
            float4 v0, v1;
            v0.x = a[j * 8 + 0] + bb0.x;
            v0.y = a[j * 8 + 1] + bb0.y;
            v0.z = a[j * 8 + 2] + bb0.z;
            v0.w = a[j * 8 + 3] + bb0.w;
            v1.x = a[j * 8 + 4] + bb1.x;
            v1.y = a[j * 8 + 5] + bb1.y;
            v1.z = a[j * 8 + 6] + bb1.z;
            v1.w = a[j * 8 + 7] + bb1.w;
            sv4[2 * cidx + 0] = v0;
            sv4[2 * cidx + 1] = v1;
        }
    }
    __syncthreads();

    // ---------------- Phase B1: radix select of rank-CAND_ threshold --------
    unsigned int prefix = 0;
    int above = 0;
#pragma unroll 1
    for (int level = 0; level < 4; level++) {
        const int shift = 24 - level * 8;
        const unsigned int mask = (level == 0) ? 0u : (0xFFFFFFFFu << (shift + 8));

        hist[tid] = 0;
        __syncthreads();
        for (int o = tid; o < OUT_; o += 256) {
            unsigned int key = flipf(svals[o]);
            if ((key & mask) == prefix)
                atomicAdd(&hist[(key >> shift) & 0xFFu], 1u);
        }
        __syncthreads();
        // inclusive suffix sum
        for (int d = 1; d < 256; d <<= 1) {
            unsigned int v = hist[tid];
            unsigned int w = (tid + d < 256) ? hist[tid + d] : 0u;
            __syncthreads();
            hist[tid] = v + w;
            __syncthreads();
        }
        {
            unsigned int ss  = hist[tid];
            unsigned int ssn = (tid < 255) ? hist[tid + 1] : 0u;
            if (above + (int)ss >= CAND_ && above + (int)ssn < CAND_)
                s_t = tid;
        }
        __syncthreads();
        const int t = s_t;
        above += (t < 255) ? (int)hist[t + 1] : 0;
        prefix |= ((unsigned int)t) << shift;
        __syncthreads();
    }
    const unsigned int T = prefix;

    // ---------------- Phase B2: emit candidate output indices ---------------
    for (int o = tid; o < OUT_; o += 256) {
        unsigned int key = flipf(svals[o]);
        if (key >= T) {
            int pos = atomicAdd(&s_cnt, 1);
            if (pos < 128) g_cand[b][pos] = (unsigned int)o;
        }
    }
    __syncthreads();
    if (tid == 0) g_cnt[b] = (s_cnt < 128) ? s_cnt : 128;
}

// ---------------------------------------------------------------------------
// Kernel 3: exact fp32 fixup of candidates + final top-64 sort + output.
// One block (128 threads, 4 warps) per b.
// ---------------------------------------------------------------------------
__global__ __launch_bounds__(128) void fixup_kernel(
    const float* __restrict__ x,
    const float* __restrict__ W,
    const float* __restrict__ bias,
    const int*   __restrict__ prev_idx,
    float*       __restrict__ out,
    int write_indices)
{
    __shared__ float sx[KDIM];
    __shared__ int   sidx[KDIM];
    __shared__ unsigned long long sel[128];

    const int b    = blockIdx.x;
    const int tid  = threadIdx.x;
    const int warp = tid >> 5;
    const int lane = tid & 31;

    if (tid < KDIM) {
        sx[tid]   = x[b * KDIM + tid];
        sidx[tid] = prev_idx[b * KDIM + tid];
    }
    sel[tid] = 0ull;
    __syncthreads();

    const int n = g_cnt[b];

    // Each warp handles candidates warp, warp+4, ... Process pairs for MLP.
    for (int c = warp; c < 128; c += 8) {
        const int c2 = c + 4;
        const bool v1 = (c < n), v2 = (c2 < n);
        int o1 = v1 ? (int)g_cand[b][c]  : 0;
        int o2 = v2 ? (int)g_cand[b][c2] : 0;
        const float* r1 = W + (size_t)o1 * IN_;
        const float* r2 = W + (size_t)o2 * IN_;
        const int i0 = sidx[lane], i1 = sidx[lane + 32];
        const float x0 = sx[lane], x1 = sx[lane + 32];

        float s1 = 0.f, s2 = 0.f;
        if (v1) s1 = r1[i0] * x0 + r1[i1] * x1;
        if (v2) s2 = r2[i0] * x0 + r2[i1] * x1;
#pragma unroll
        for (int d = 16; d > 0; d >>= 1) {
            s1 += __shfl_xor_sync(0xFFFFFFFFu, s1, d);
            s2 += __shfl_xor_sync(0xFFFFFFFFu, s2, d);
        }
        if (lane == 0) {
            if (v1) {
                float val = s1 + bias[o1];
                sel[c] = ((unsigned long long)flipf(val) << 32) |
                         (unsigned long long)(0xFFFFFFFFu - (unsigned int)o1);
            }
            if (v2) {
                float val2 = s2 + bias[o2];
                sel[c2] = ((unsigned long long)flipf(val2) << 32) |
                          (unsigned long long)(0xFFFFFFFFu - (unsigned int)o2);
            }
        }
    }
    __syncthreads();

    // Bitonic sort 128 descending (packed key: larger = bigger val, then smaller o)
    for (int size = 2; size <= 128; size <<= 1) {
        for (int stride = size >> 1; stride > 0; stride >>= 1) {
            int partner = tid ^ stride;
            if (partner > tid) {
                unsigned long long va = sel[tid], vb = sel[partner];
                bool desc = ((tid & size) == 0);
                if (desc ? (va < vb) : (va > vb)) {
                    sel[tid] = vb;
                    sel[partner] = va;
                }
            }
            __syncthreads();
        }
    }

    if (tid < TOPK_) {
        unsigned long long p = sel[tid];
        unsigned int key = (unsigned int)(p >> 32);
        unsigned int idx = 0xFFFFFFFFu - (unsigned int)(p & 0xFFFFFFFFull);
        out[b * TOPK_ + tid] = unflipf(key);
        if (write_indices)
            out[(size_t)B_ * TOPK_ + b * TOPK_ + tid] = (float)idx;
    }
}

// ---------------------------------------------------------------------------
extern "C" void kernel_launch(void* const* d_in, const int* in_sizes, int n_in,
                              void* d_out, int out_size) {
    const float* x        = (const float*)d_in[0];  // (B, K) f32
    const float* W        = (const float*)d_in[1];  // (OUT, IN) f32
    const float* bias     = (const float*)d_in[2];  // (OUT,) f32
    const int*   prev_idx = (const int*)d_in[3];    // (B, K) i32
    float* out = (float*)d_out;

    int write_indices = (out_size >= 2 * B_ * TOPK_) ? 1 : 0;

    transpose16_kernel<<<dim3(IN_ / 64, OUT_ / 64), 256>>>(W);
    gather16_kernel<<<B_, 256>>>(x, bias, prev_idx);
    fixup_kernel<<<B_, 128>>>(x, W, bias, prev_idx, out, write_indices);
}